// round 1
// baseline (speedup 1.0000x reference)
#include <cuda_runtime.h>
#include <cuda_bf16.h>
#include <math.h>

typedef unsigned long long ull;

// ---------------- packed f32x2 helpers ----------------
__device__ __forceinline__ ull pack2(float x, float y) {
    ull r; asm("mov.b64 %0, {%1, %2};" : "=l"(r) : "f"(x), "f"(y)); return r;
}
__device__ __forceinline__ float2 unpack2(ull v) {
    float2 r; asm("mov.b64 {%0, %1}, %2;" : "=f"(r.x), "=f"(r.y) : "l"(v)); return r;
}
__device__ __forceinline__ void ffma2(ull& c, ull a, ull b) {
    asm("fma.rn.f32x2 %0, %1, %2, %0;" : "+l"(c) : "l"(a), "l"(b));
}
__device__ __forceinline__ void fmul2(ull& c, ull a) {
    asm("mul.rn.f32x2 %0, %0, %1;" : "+l"(c) : "l"(a));
}

// ---------------- problem constants ----------------
#define BATCH 4
#define SEQ   2048
#define DMODEL 1024
#define NHEADS 16
#define HDIM  64
#define ROWS  (BATCH * SEQ)          // 8192
#define QKV_LD 3072

// scratch (device globals: allocation-free per harness rules)
__device__ float g_qkv[(size_t)ROWS * QKV_LD];   // [row][3072]: Q | K | V
__device__ float g_ctx[(size_t)ROWS * DMODEL];   // attention output

// =====================================================================
// GEMM: C[M,N] = A[M,K] @ B[K,N] (+ bias), fp32 with f32x2 FMA.
// 128x128 block tile, BK=16, 256 threads, 8x8 per-thread (4 row-pairs x 8).
// =====================================================================
__global__ __launch_bounds__(256, 2)
void gemm_f32(const float* __restrict__ A, const float* __restrict__ B,
              float* __restrict__ C, const float* __restrict__ bias,
              int M, int N, int K, int lda, int ldb, int ldc)
{
    __shared__ float As[16][128];   // [k][m]
    __shared__ float Bs[16][128];   // [k][n]

    const int tid = threadIdx.x;
    const int tx = tid & 15;        // 0..15 -> 8 cols each
    const int ty = tid >> 4;        // 0..15 -> 8 rows each
    const int m0 = blockIdx.y << 7;
    const int n0 = blockIdx.x << 7;

    const int ar = tid >> 2;            // 0..63 (A tile row)
    const int ac = (tid & 3) << 2;      // k offset 0,4,8,12
    const int br = tid >> 5;            // 0..7  (B tile k-row)
    const int bc = (tid & 31) << 2;     // n offset

    const float* Aptr = A + (size_t)(m0 + ar) * lda + ac;
    const float* Bptr = B + (size_t)br * ldb + n0 + bc;

    ull acc[4][8];
    #pragma unroll
    for (int i = 0; i < 4; ++i)
        #pragma unroll
        for (int j = 0; j < 8; ++j) acc[i][j] = 0ull;

    for (int k0 = 0; k0 < K; k0 += 16) {
        #pragma unroll
        for (int r = 0; r < 2; ++r) {
            float4 a4 = *(const float4*)(Aptr + (size_t)(r * 64) * lda + k0);
            As[ac + 0][ar + r * 64] = a4.x;
            As[ac + 1][ar + r * 64] = a4.y;
            As[ac + 2][ar + r * 64] = a4.z;
            As[ac + 3][ar + r * 64] = a4.w;
        }
        #pragma unroll
        for (int r = 0; r < 2; ++r) {
            float4 b4 = *(const float4*)(Bptr + (size_t)(k0 + r * 8) * ldb);
            *(float4*)&Bs[br + r * 8][bc] = b4;
        }
        __syncthreads();

        #pragma unroll
        for (int kk = 0; kk < 16; ++kk) {
            ull a2[4];
            #pragma unroll
            for (int i2 = 0; i2 < 4; ++i2)
                a2[i2] = *(const ull*)&As[kk][ty * 8 + i2 * 2];
            float4 b0 = *(const float4*)&Bs[kk][tx * 8];
            float4 b1 = *(const float4*)&Bs[kk][tx * 8 + 4];
            ull bd[8];
            bd[0] = pack2(b0.x, b0.x); bd[1] = pack2(b0.y, b0.y);
            bd[2] = pack2(b0.z, b0.z); bd[3] = pack2(b0.w, b0.w);
            bd[4] = pack2(b1.x, b1.x); bd[5] = pack2(b1.y, b1.y);
            bd[6] = pack2(b1.z, b1.z); bd[7] = pack2(b1.w, b1.w);
            #pragma unroll
            for (int i2 = 0; i2 < 4; ++i2)
                #pragma unroll
                for (int j = 0; j < 8; ++j)
                    ffma2(acc[i2][j], a2[i2], bd[j]);
        }
        __syncthreads();
    }

    // epilogue
    float bv[8];
    #pragma unroll
    for (int j = 0; j < 8; ++j)
        bv[j] = bias ? bias[n0 + tx * 8 + j] : 0.0f;

    #pragma unroll
    for (int i2 = 0; i2 < 4; ++i2) {
        float o0[8], o1[8];
        #pragma unroll
        for (int j = 0; j < 8; ++j) {
            float2 v = unpack2(acc[i2][j]);
            o0[j] = v.x + bv[j];
            o1[j] = v.y + bv[j];
        }
        float* c0 = C + (size_t)(m0 + ty * 8 + i2 * 2) * ldc + n0 + tx * 8;
        float* c1 = c0 + ldc;
        *(float4*)(c0)     = make_float4(o0[0], o0[1], o0[2], o0[3]);
        *(float4*)(c0 + 4) = make_float4(o0[4], o0[5], o0[6], o0[7]);
        *(float4*)(c1)     = make_float4(o1[0], o1[1], o1[2], o1[3]);
        *(float4*)(c1 + 4) = make_float4(o1[4], o1[5], o1[6], o1[7]);
    }
}

// =====================================================================
// Flash attention (causal), fp32. One block = 128 q rows of one (b,h).
// BN=64 kv per tile. 256 threads: tx(16)->4 cols, ty(16)->8 rows.
// smem: QsT[64][128] (e-major), KsT[64][65] (e-major), Vs[64][68],
//       PsT[64][130] (kv-major, row-paired loads).
// =====================================================================
#define Q_STRIDE 128
#define K_STRIDE 65
#define V_STRIDE 68
#define P_STRIDE 130
#define ATT_SMEM_FLOATS (64*Q_STRIDE + 64*K_STRIDE + 64*V_STRIDE + 64*P_STRIDE)
#define ATT_SMEM_BYTES  (ATT_SMEM_FLOATS * 4)

__global__ __launch_bounds__(256, 1)
void attn_kernel(const float* __restrict__ qkv, float* __restrict__ ctx)
{
    extern __shared__ float sm[];
    float* QsT = sm;                       // [e][128]
    float* KsT = QsT + 64 * Q_STRIDE;      // [e][65]
    float* Vs  = KsT + 64 * K_STRIDE;      // [kv][68]
    float* PsT = Vs  + 64 * V_STRIDE;      // [kv][130]

    const int tid = threadIdx.x;
    const int tx = tid & 15;
    const int ty = tid >> 4;
    const int q0 = blockIdx.x << 7;
    const int bh = blockIdx.y;
    const int bb = bh >> 4, hh = bh & 15;

    const float* qbase = qkv + (size_t)bb * SEQ * QKV_LD + hh * HDIM;
    const float* kbase = qbase + 1024;
    const float* vbase = qbase + 2048;

    // load Q tile transposed: QsT[e][r]
    {
        const int r  = tid >> 4;
        const int e  = (tid & 15) << 2;
        #pragma unroll
        for (int it = 0; it < 8; ++it) {
            int rr = r + it * 16;
            float4 v = *(const float4*)(qbase + (size_t)(q0 + rr) * QKV_LD + e);
            QsT[(e + 0) * Q_STRIDE + rr] = v.x;
            QsT[(e + 1) * Q_STRIDE + rr] = v.y;
            QsT[(e + 2) * Q_STRIDE + rr] = v.z;
            QsT[(e + 3) * Q_STRIDE + rr] = v.w;
        }
    }

    float m_i[8], l_i[8], corr[8];
    ull o2[4][4];
    #pragma unroll
    for (int r = 0; r < 8; ++r) { m_i[r] = -1e30f; l_i[r] = 0.0f; }
    #pragma unroll
    for (int i2 = 0; i2 < 4; ++i2)
        #pragma unroll
        for (int j = 0; j < 4; ++j) o2[i2][j] = 0ull;

    const float SCL = 0.125f * 1.4426950408889634f;  // (1/sqrt(hd)) * log2(e)
    const int ntiles = (q0 >> 6) + 2;

    for (int t = 0; t < ntiles; ++t) {
        const int j0 = t << 6;
        __syncthreads();   // prior PV readers of Vs/PsT done
        // load K (transposed) and V tiles
        {
            const int r = tid >> 4;
            const int e = (tid & 15) << 2;
            #pragma unroll
            for (int it = 0; it < 4; ++it) {
                int rr = r + it * 16;
                float4 k4 = *(const float4*)(kbase + (size_t)(j0 + rr) * QKV_LD + e);
                KsT[(e + 0) * K_STRIDE + rr] = k4.x;
                KsT[(e + 1) * K_STRIDE + rr] = k4.y;
                KsT[(e + 2) * K_STRIDE + rr] = k4.z;
                KsT[(e + 3) * K_STRIDE + rr] = k4.w;
                float4 v4 = *(const float4*)(vbase + (size_t)(j0 + rr) * QKV_LD + e);
                *(float4*)&Vs[rr * V_STRIDE + e] = v4;
            }
        }
        __syncthreads();

        // S = Q K^T  (row-paired f32x2 accumulation)
        ull s2[4][4];
        #pragma unroll
        for (int i2 = 0; i2 < 4; ++i2)
            #pragma unroll
            for (int j = 0; j < 4; ++j) s2[i2][j] = 0ull;

        #pragma unroll 8
        for (int e = 0; e < 64; ++e) {
            const float* qrow = &QsT[e * Q_STRIDE + ty * 8];
            const float* krow = &KsT[e * K_STRIDE + tx * 4];
            ull a2[4];
            a2[0] = *(const ull*)(qrow + 0);
            a2[1] = *(const ull*)(qrow + 2);
            a2[2] = *(const ull*)(qrow + 4);
            a2[3] = *(const ull*)(qrow + 6);
            ull kd[4];
            kd[0] = pack2(krow[0], krow[0]);
            kd[1] = pack2(krow[1], krow[1]);
            kd[2] = pack2(krow[2], krow[2]);
            kd[3] = pack2(krow[3], krow[3]);
            #pragma unroll
            for (int i2 = 0; i2 < 4; ++i2)
                #pragma unroll
                for (int j = 0; j < 4; ++j)
                    ffma2(s2[i2][j], a2[i2], kd[j]);
        }

        // online softmax per local row (reductions over 16-lane groups)
        const bool need_mask = (t >= ntiles - 2);
        #pragma unroll
        for (int rloc = 0; rloc < 8; ++rloc) {
            const int i2 = rloc >> 1, hlf = rloc & 1;
            const int grow = q0 + ty * 8 + rloc;
            float u[4];
            #pragma unroll
            for (int j = 0; j < 4; ++j) {
                float2 v = unpack2(s2[i2][j]);
                float sv = hlf ? v.y : v.x;
                int gcol = j0 + tx * 4 + j;
                u[j] = (need_mask && (gcol > grow)) ? -1e30f : sv * SCL;
            }
            float tm = fmaxf(fmaxf(u[0], u[1]), fmaxf(u[2], u[3]));
            tm = fmaxf(tm, __shfl_xor_sync(0xffffffffu, tm, 1));
            tm = fmaxf(tm, __shfl_xor_sync(0xffffffffu, tm, 2));
            tm = fmaxf(tm, __shfl_xor_sync(0xffffffffu, tm, 4));
            tm = fmaxf(tm, __shfl_xor_sync(0xffffffffu, tm, 8));
            float mn = fmaxf(m_i[rloc], tm);
            float c  = exp2f(m_i[rloc] - mn);
            float ps = 0.0f;
            #pragma unroll
            for (int j = 0; j < 4; ++j) {
                float p = exp2f(u[j] - mn);
                PsT[(tx * 4 + j) * P_STRIDE + ty * 8 + rloc] = p;
                ps += p;
            }
            ps += __shfl_xor_sync(0xffffffffu, ps, 1);
            ps += __shfl_xor_sync(0xffffffffu, ps, 2);
            ps += __shfl_xor_sync(0xffffffffu, ps, 4);
            ps += __shfl_xor_sync(0xffffffffu, ps, 8);
            l_i[rloc] = l_i[rloc] * c + ps;
            m_i[rloc] = mn;
            corr[rloc] = c;
        }
        // rescale O accumulators
        #pragma unroll
        for (int i2 = 0; i2 < 4; ++i2) {
            ull c2 = pack2(corr[2 * i2], corr[2 * i2 + 1]);
            #pragma unroll
            for (int j = 0; j < 4; ++j) fmul2(o2[i2][j], c2);
        }
        __syncthreads();   // PsT fully written

        // O += P V
        #pragma unroll 8
        for (int j2 = 0; j2 < 64; ++j2) {
            const float* prow = &PsT[j2 * P_STRIDE + ty * 8];
            const float* vrow = &Vs[j2 * V_STRIDE + tx * 4];
            ull p2[4];
            p2[0] = *(const ull*)(prow + 0);
            p2[1] = *(const ull*)(prow + 2);
            p2[2] = *(const ull*)(prow + 4);
            p2[3] = *(const ull*)(prow + 6);
            ull vd[4];
            vd[0] = pack2(vrow[0], vrow[0]);
            vd[1] = pack2(vrow[1], vrow[1]);
            vd[2] = pack2(vrow[2], vrow[2]);
            vd[3] = pack2(vrow[3], vrow[3]);
            #pragma unroll
            for (int i2 = 0; i2 < 4; ++i2)
                #pragma unroll
                for (int j = 0; j < 4; ++j)
                    ffma2(o2[i2][j], p2[i2], vd[j]);
        }
    }

    // epilogue: ctx[b*2048 + q][h*64 + e] = o / l
    float* obase = ctx + (size_t)(bb * SEQ + q0) * DMODEL + hh * HDIM;
    #pragma unroll
    for (int i2 = 0; i2 < 4; ++i2) {
        float inv0 = 1.0f / l_i[2 * i2];
        float inv1 = 1.0f / l_i[2 * i2 + 1];
        float r0[4], r1[4];
        #pragma unroll
        for (int j = 0; j < 4; ++j) {
            float2 v = unpack2(o2[i2][j]);
            r0[j] = v.x * inv0;
            r1[j] = v.y * inv1;
        }
        *(float4*)(obase + (size_t)(ty * 8 + 2 * i2) * DMODEL + tx * 4) =
            make_float4(r0[0], r0[1], r0[2], r0[3]);
        *(float4*)(obase + (size_t)(ty * 8 + 2 * i2 + 1) * DMODEL + tx * 4) =
            make_float4(r1[0], r1[1], r1[2], r1[3]);
    }
}

// =====================================================================
extern "C" void kernel_launch(void* const* d_in, const int* in_sizes, int n_in,
                              void* d_out, int out_size)
{
    const float* x  = (const float*)d_in[0];
    const float* Wq = (const float*)d_in[1];
    const float* Wk = (const float*)d_in[2];
    const float* Wv = (const float*)d_in[3];
    const float* Wo = (const float*)d_in[4];
    const float* bo = (const float*)d_in[5];
    float* out = (float*)d_out;

    float* qkv = nullptr;
    float* ctx = nullptr;
    cudaGetSymbolAddress((void**)&qkv, g_qkv);
    cudaGetSymbolAddress((void**)&ctx, g_ctx);
    cudaFuncSetAttribute(attn_kernel,
                         cudaFuncAttributeMaxDynamicSharedMemorySize, ATT_SMEM_BYTES);

    dim3 gproj(DMODEL / 128, ROWS / 128);   // (8, 64)
    gemm_f32<<<gproj, 256>>>(x, Wq, qkv + 0,    nullptr, ROWS, DMODEL, DMODEL, DMODEL, DMODEL, QKV_LD);
    gemm_f32<<<gproj, 256>>>(x, Wk, qkv + 1024, nullptr, ROWS, DMODEL, DMODEL, DMODEL, DMODEL, QKV_LD);
    gemm_f32<<<gproj, 256>>>(x, Wv, qkv + 2048, nullptr, ROWS, DMODEL, DMODEL, DMODEL, DMODEL, QKV_LD);

    attn_kernel<<<dim3(SEQ / 128, BATCH * NHEADS), 256, ATT_SMEM_BYTES>>>(qkv, ctx);

    gemm_f32<<<gproj, 256>>>(ctx, Wo, out, bo, ROWS, DMODEL, DMODEL, DMODEL, DMODEL, DMODEL);
}

// round 4
// speedup vs baseline: 2.2042x; 2.2042x over previous
#include <cuda_runtime.h>
#include <cuda_bf16.h>
#include <cstdint>
#include <math.h>

// R4: identical to R3 candidate — R3 failed on infra (container), never ran.

// =====================================================================
// helpers
// =====================================================================
__device__ __forceinline__ uint32_t smem_to_u32(const void* smem_ptr) {
    uint32_t addr;
    asm("{ .reg .u64 tmp; cvta.to.shared.u64 tmp, %1; cvt.u32.u64 %0, tmp; }"
        : "=r"(addr) : "l"(smem_ptr));
    return addr;
}
__device__ __forceinline__ uint32_t f2tf32(float f) {
    uint32_t r; asm("cvt.rna.tf32.f32 %0, %1;" : "=r"(r) : "f"(f)); return r;
}
// D += A(16x8) * B(8x8), tf32 inputs (b32 regs), fp32 accumulate
__device__ __forceinline__ void mma_tf32(float* d, const uint32_t* a, const uint32_t* b) {
    asm volatile(
        "mma.sync.aligned.m16n8k8.row.col.f32.tf32.tf32.f32 "
        "{%0,%1,%2,%3}, {%4,%5,%6,%7}, {%8,%9}, {%0,%1,%2,%3};"
        : "+f"(d[0]), "+f"(d[1]), "+f"(d[2]), "+f"(d[3])
        : "r"(a[0]), "r"(a[1]), "r"(a[2]), "r"(a[3]), "r"(b[0]), "r"(b[1]));
}
#define CP_ASYNC16(dst, src) \
    asm volatile("cp.async.cg.shared.global [%0], [%1], 16;" \
                 :: "r"(dst), "l"(src) : "memory")
#define CP_COMMIT() asm volatile("cp.async.commit_group;" ::: "memory")
#define CP_WAIT(n)  asm volatile("cp.async.wait_group %0;" :: "n"(n) : "memory")

// ---------------- problem constants ----------------
#define BATCH 4
#define SEQ   2048
#define DMODEL 1024
#define NHEADS 16
#define HDIM  64
#define ROWS  (BATCH * SEQ)          // 8192
#define QKV_LD 3072

// scratch (device globals: allocation-free per harness rules)
__device__ float g_qkv[(size_t)ROWS * QKV_LD];    // [row][3072]: Q | K | V
__device__ float g_ctx[(size_t)ROWS * DMODEL];    // attention output (tf32-rounded)
__device__ float g_bt[(size_t)3072 * DMODEL];     // [Wq^T; Wk^T; Wv^T] (N,K), tf32-rounded
__device__ float g_wot[(size_t)DMODEL * DMODEL];  // Wo^T (N,K), tf32-rounded
__device__ float g_xr[(size_t)ROWS * DMODEL];     // x, tf32-rounded

// =====================================================================
// transpose + tf32-round: dst[c][r] = round(src[r][c]), 1024x1024
// =====================================================================
__global__ void transpose_1024(const float* __restrict__ src, float* __restrict__ dst)
{
    __shared__ float tile[32][33];
    int x = blockIdx.x * 32 + threadIdx.x;
    int y = blockIdx.y * 32 + threadIdx.y;
    #pragma unroll
    for (int i = 0; i < 32; i += 8)
        tile[threadIdx.y + i][threadIdx.x] = src[(size_t)(y + i) * 1024 + x];
    __syncthreads();
    x = blockIdx.y * 32 + threadIdx.x;
    y = blockIdx.x * 32 + threadIdx.y;
    #pragma unroll
    for (int i = 0; i < 32; i += 8)
        dst[(size_t)(y + i) * 1024 + x] =
            __uint_as_float(f2tf32(tile[threadIdx.x][threadIdx.y + i]));
}

// elementwise tf32 round (for activation matrix)
__global__ void round_tf32(const float* __restrict__ src, float* __restrict__ dst)
{
    size_t i = ((size_t)blockIdx.x * blockDim.x + threadIdx.x) * 4;
    float4 v = *(const float4*)(src + i);
    v.x = __uint_as_float(f2tf32(v.x));
    v.y = __uint_as_float(f2tf32(v.y));
    v.z = __uint_as_float(f2tf32(v.z));
    v.w = __uint_as_float(f2tf32(v.w));
    *(float4*)(dst + i) = v;
}

// =====================================================================
// tf32 mma.sync GEMM: C[M,N] = A[M,K] @ Bt[N,K]^T (+ bias)
// 128x128 tile, BK=32, 3-stage cp.async, 256 threads, warps 4Mx2N (32x64 each)
// A, Bt must be pre-rounded to tf32.
// =====================================================================
#define G_STR 36                       // smem row stride (floats), conflict-free
#define G_STAGE (128 * G_STR)          // per-matrix per-stage u32 count
#define GEMM_SMEM_BYTES (3 * 2 * G_STAGE * 4)   // 110592

__global__ __launch_bounds__(256, 1)
void gemm_mma(const float* __restrict__ A, const float* __restrict__ Bt,
              float* __restrict__ C, const float* __restrict__ bias,
              int M, int N, int K, int lda, int ldb, int ldc)
{
    extern __shared__ uint32_t smg[];
    const int tid = threadIdx.x, lane = tid & 31, wid = tid >> 5;
    const int warpM = wid >> 1, warpN = wid & 1;
    const int m0 = blockIdx.y << 7, n0 = blockIdx.x << 7;
    uint32_t* As = smg;                  // [3][128*36]
    uint32_t* Bs = smg + 3 * G_STAGE;

    const int lr = tid >> 1;             // 0..127
    const int lc = (tid & 1) << 4;       // 0 or 16
    const float* Ag = A  + (size_t)(m0 + lr) * lda + lc;
    const float* Bg = Bt + (size_t)(n0 + lr) * ldb + lc;
    const uint32_t a_sm = smem_to_u32(As) + (uint32_t)(lr * G_STR + lc) * 4u;
    const uint32_t b_sm = smem_to_u32(Bs) + (uint32_t)(lr * G_STR + lc) * 4u;
    const int nch = K >> 5;

    auto load_stage = [&](int t) {
        const uint32_t off = (uint32_t)(t % 3) * G_STAGE * 4u;
        const float* ag = Ag + t * 32;
        const float* bg = Bg + t * 32;
        #pragma unroll
        for (int i = 0; i < 4; ++i) CP_ASYNC16(a_sm + off + i * 16, ag + i * 4);
        #pragma unroll
        for (int i = 0; i < 4; ++i) CP_ASYNC16(b_sm + off + i * 16, bg + i * 4);
        CP_COMMIT();
    };

    float acc[2][8][4];
    #pragma unroll
    for (int mt = 0; mt < 2; ++mt)
        #pragma unroll
        for (int nt = 0; nt < 8; ++nt)
            #pragma unroll
            for (int j = 0; j < 4; ++j) acc[mt][nt][j] = 0.0f;

    load_stage(0); load_stage(1); load_stage(2);

    const int r0 = lane >> 2, c0 = lane & 3;
    for (int t = 0; t < nch; ++t) {
        CP_WAIT(2);
        __syncthreads();
        const uint32_t* Ab = As + (t % 3) * G_STAGE;
        const uint32_t* Bb = Bs + (t % 3) * G_STAGE;
        #pragma unroll
        for (int ks = 0; ks < 4; ++ks) {
            const int kk = ks * 8 + c0;
            uint32_t af[2][4];
            #pragma unroll
            for (int mt = 0; mt < 2; ++mt) {
                const int mr = warpM * 32 + mt * 16 + r0;
                af[mt][0] = Ab[mr * G_STR + kk];
                af[mt][1] = Ab[(mr + 8) * G_STR + kk];
                af[mt][2] = Ab[mr * G_STR + kk + 4];
                af[mt][3] = Ab[(mr + 8) * G_STR + kk + 4];
            }
            #pragma unroll
            for (int nt = 0; nt < 8; ++nt) {
                const int nr = warpN * 64 + nt * 8 + r0;
                uint32_t bf[2];
                bf[0] = Bb[nr * G_STR + kk];
                bf[1] = Bb[nr * G_STR + kk + 4];
                mma_tf32(acc[0][nt], af[0], bf);
                mma_tf32(acc[1][nt], af[1], bf);
            }
        }
        __syncthreads();
        if (t + 3 < nch) load_stage(t + 3);
    }

    // epilogue
    #pragma unroll
    for (int mt = 0; mt < 2; ++mt) {
        const int row = m0 + warpM * 32 + mt * 16 + r0;
        #pragma unroll
        for (int nt = 0; nt < 8; ++nt) {
            const int col = n0 + warpN * 64 + nt * 8 + 2 * c0;
            float b0v = 0.0f, b1v = 0.0f;
            if (bias) { b0v = bias[col]; b1v = bias[col + 1]; }
            *(float2*)(C + (size_t)row * ldc + col) =
                make_float2(acc[mt][nt][0] + b0v, acc[mt][nt][1] + b1v);
            *(float2*)(C + (size_t)(row + 8) * ldc + col) =
                make_float2(acc[mt][nt][2] + b0v, acc[mt][nt][3] + b1v);
        }
    }
}

// =====================================================================
// Flash attention (causal), tf32 mma.sync.
// Block: 128 q rows of one (b,h), 64 kv per tile, 256 threads = 8 warps.
// Warp = 16 q rows x full 64 kv (softmax reduction stays in a lane quad).
// =====================================================================
#define AQ_STR 68
#define AK_STR 68
#define AV_STR 72
#define AP_STR 68
#define ATT_SMEM_U32 (128*AQ_STR + 64*AK_STR + 64*AV_STR + 128*AP_STR)
#define ATT_SMEM_BYTES (ATT_SMEM_U32 * 4)

__global__ __launch_bounds__(256, 1)
void attn_kernel(const float* __restrict__ qkv, float* __restrict__ ctx)
{
    extern __shared__ uint32_t sma[];
    uint32_t* Qs = sma;                      // [128][68]  (q, e) tf32
    uint32_t* Ks = Qs + 128 * AQ_STR;        // [64][68]   (kv, e) tf32
    uint32_t* Vs = Ks + 64 * AK_STR;         // [64][72]   (kv, e) tf32
    uint32_t* Ps = Vs + 64 * AV_STR;         // [128][68]  (q, kv) tf32

    const int tid = threadIdx.x, lane = tid & 31, wid = tid >> 5;
    const int q0 = blockIdx.x << 7;
    const int bh = blockIdx.y;
    const int bb = bh >> 4, hh = bh & 15;

    const float* qbase = qkv + (size_t)bb * SEQ * QKV_LD + hh * HDIM;
    const float* kbase = qbase + 1024;
    const float* vbase = qbase + 2048;

    // load Q (rounded to tf32): 2 threads/row, 32 cols each
    {
        const int r = tid >> 1, cc = (tid & 1) << 5;
        const float* src = qbase + (size_t)(q0 + r) * QKV_LD + cc;
        #pragma unroll
        for (int i = 0; i < 8; ++i) {
            float4 v = *(const float4*)(src + i * 4);
            uint32_t* d = &Qs[r * AQ_STR + cc + i * 4];
            d[0] = f2tf32(v.x); d[1] = f2tf32(v.y);
            d[2] = f2tf32(v.z); d[3] = f2tf32(v.w);
        }
    }

    const int q0w = wid << 4;          // warp's q row base (0..112)
    const int r0 = lane >> 2, c0 = lane & 3;
    float m_i[2] = {-1e30f, -1e30f}, l_i[2] = {0.0f, 0.0f};
    float oacc[8][4];
    #pragma unroll
    for (int nt = 0; nt < 8; ++nt)
        #pragma unroll
        for (int j = 0; j < 4; ++j) oacc[nt][j] = 0.0f;

    const float SCL = 0.125f * 1.4426950408889634f;   // (1/sqrt(64)) * log2(e)
    const int ntiles = (q0 >> 6) + 2;

    for (int t = 0; t < ntiles; ++t) {
        const int j0 = t << 6;
        __syncthreads();    // prior PV readers of Ks/Vs done
        // load K, V (rounded): 4 threads/row, 16 cols each
        {
            const int r = tid >> 2, cc = (tid & 3) << 4;
            const float* ksrc = kbase + (size_t)(j0 + r) * QKV_LD + cc;
            const float* vsrc = vbase + (size_t)(j0 + r) * QKV_LD + cc;
            #pragma unroll
            for (int i = 0; i < 4; ++i) {
                float4 kv = *(const float4*)(ksrc + i * 4);
                uint32_t* dk = &Ks[r * AK_STR + cc + i * 4];
                dk[0] = f2tf32(kv.x); dk[1] = f2tf32(kv.y);
                dk[2] = f2tf32(kv.z); dk[3] = f2tf32(kv.w);
                float4 vv = *(const float4*)(vsrc + i * 4);
                uint32_t* dv = &Vs[r * AV_STR + cc + i * 4];
                dv[0] = f2tf32(vv.x); dv[1] = f2tf32(vv.y);
                dv[2] = f2tf32(vv.z); dv[3] = f2tf32(vv.w);
            }
        }
        __syncthreads();

        // ---- S = Q K^T ----
        float sacc[8][4];
        #pragma unroll
        for (int nt = 0; nt < 8; ++nt)
            #pragma unroll
            for (int j = 0; j < 4; ++j) sacc[nt][j] = 0.0f;

        #pragma unroll
        for (int ks = 0; ks < 8; ++ks) {
            const int kk = ks * 8 + c0;
            uint32_t af[4];
            af[0] = Qs[(q0w + r0) * AQ_STR + kk];
            af[1] = Qs[(q0w + r0 + 8) * AQ_STR + kk];
            af[2] = Qs[(q0w + r0) * AQ_STR + kk + 4];
            af[3] = Qs[(q0w + r0 + 8) * AQ_STR + kk + 4];
            #pragma unroll
            for (int nt = 0; nt < 8; ++nt) {
                uint32_t bf[2];
                bf[0] = Ks[(nt * 8 + r0) * AK_STR + kk];
                bf[1] = Ks[(nt * 8 + r0) * AK_STR + kk + 4];
                mma_tf32(sacc[nt], af, bf);
            }
        }

        // ---- online softmax (2 rows per thread) ----
        const bool need_mask = (t >= ntiles - 2);
        float corr[2];
        #pragma unroll
        for (int h = 0; h < 2; ++h) {
            const int grow = q0 + q0w + r0 + h * 8;
            float u[8][2];
            float rmax = -1e30f;
            #pragma unroll
            for (int nt = 0; nt < 8; ++nt) {
                float v0 = sacc[nt][h * 2 + 0] * SCL;
                float v1 = sacc[nt][h * 2 + 1] * SCL;
                if (need_mask) {
                    const int gc = j0 + nt * 8 + 2 * c0;
                    if (gc > grow)     v0 = -1e30f;
                    if (gc + 1 > grow) v1 = -1e30f;
                }
                u[nt][0] = v0; u[nt][1] = v1;
                rmax = fmaxf(rmax, fmaxf(v0, v1));
            }
            rmax = fmaxf(rmax, __shfl_xor_sync(0xffffffffu, rmax, 1));
            rmax = fmaxf(rmax, __shfl_xor_sync(0xffffffffu, rmax, 2));
            const float mn = fmaxf(m_i[h], rmax);
            const float c = exp2f(m_i[h] - mn);
            float psum = 0.0f;
            #pragma unroll
            for (int nt = 0; nt < 8; ++nt) {
                const float p0 = exp2f(u[nt][0] - mn);
                const float p1 = exp2f(u[nt][1] - mn);
                psum += p0 + p1;
                uint32_t* dst = &Ps[(q0w + r0 + h * 8) * AP_STR + nt * 8 + 2 * c0];
                dst[0] = f2tf32(p0); dst[1] = f2tf32(p1);
            }
            psum += __shfl_xor_sync(0xffffffffu, psum, 1);
            psum += __shfl_xor_sync(0xffffffffu, psum, 2);
            l_i[h] = l_i[h] * c + psum;
            m_i[h] = mn;
            corr[h] = c;
        }
        __syncwarp();   // Ps rows of this warp visible to all its lanes

        // rescale O accumulators
        #pragma unroll
        for (int nt = 0; nt < 8; ++nt) {
            oacc[nt][0] *= corr[0]; oacc[nt][1] *= corr[0];
            oacc[nt][2] *= corr[1]; oacc[nt][3] *= corr[1];
        }

        // ---- O += P V ----
        #pragma unroll
        for (int ks = 0; ks < 8; ++ks) {
            const int kk = ks * 8 + c0;
            uint32_t af[4];
            af[0] = Ps[(q0w + r0) * AP_STR + kk];
            af[1] = Ps[(q0w + r0 + 8) * AP_STR + kk];
            af[2] = Ps[(q0w + r0) * AP_STR + kk + 4];
            af[3] = Ps[(q0w + r0 + 8) * AP_STR + kk + 4];
            #pragma unroll
            for (int nt = 0; nt < 8; ++nt) {
                uint32_t bf[2];
                bf[0] = Vs[kk * AV_STR + nt * 8 + r0];
                bf[1] = Vs[(kk + 4) * AV_STR + nt * 8 + r0];
                mma_tf32(oacc[nt], af, bf);
            }
        }
    }

    // epilogue: ctx (tf32-rounded for next GEMM)
    float* obase = ctx + (size_t)(bb * SEQ + q0 + q0w) * DMODEL + hh * HDIM;
    const float inv0 = 1.0f / l_i[0];
    const float inv1 = 1.0f / l_i[1];
    #pragma unroll
    for (int nt = 0; nt < 8; ++nt) {
        const int col = nt * 8 + 2 * c0;
        float2 w0 = make_float2(
            __uint_as_float(f2tf32(oacc[nt][0] * inv0)),
            __uint_as_float(f2tf32(oacc[nt][1] * inv0)));
        float2 w1 = make_float2(
            __uint_as_float(f2tf32(oacc[nt][2] * inv1)),
            __uint_as_float(f2tf32(oacc[nt][3] * inv1)));
        *(float2*)(obase + (size_t)r0 * DMODEL + col) = w0;
        *(float2*)(obase + (size_t)(r0 + 8) * DMODEL + col) = w1;
    }
}

// =====================================================================
extern "C" void kernel_launch(void* const* d_in, const int* in_sizes, int n_in,
                              void* d_out, int out_size)
{
    const float* x  = (const float*)d_in[0];
    const float* Wq = (const float*)d_in[1];
    const float* Wk = (const float*)d_in[2];
    const float* Wv = (const float*)d_in[3];
    const float* Wo = (const float*)d_in[4];
    const float* bo = (const float*)d_in[5];
    float* out = (float*)d_out;

    float *qkv = nullptr, *ctx = nullptr, *bt = nullptr, *wot = nullptr, *xr = nullptr;
    cudaGetSymbolAddress((void**)&qkv, g_qkv);
    cudaGetSymbolAddress((void**)&ctx, g_ctx);
    cudaGetSymbolAddress((void**)&bt,  g_bt);
    cudaGetSymbolAddress((void**)&wot, g_wot);
    cudaGetSymbolAddress((void**)&xr,  g_xr);
    cudaFuncSetAttribute(attn_kernel,
                         cudaFuncAttributeMaxDynamicSharedMemorySize, ATT_SMEM_BYTES);
    cudaFuncSetAttribute(gemm_mma,
                         cudaFuncAttributeMaxDynamicSharedMemorySize, GEMM_SMEM_BYTES);

    dim3 tb(32, 8), tg(32, 32);
    transpose_1024<<<tg, tb>>>(Wq, bt + 0 * 1024 * 1024);
    transpose_1024<<<tg, tb>>>(Wk, bt + 1 * 1024 * 1024);
    transpose_1024<<<tg, tb>>>(Wv, bt + 2 * 1024 * 1024);
    transpose_1024<<<tg, tb>>>(Wo, wot);
    round_tf32<<<(ROWS * DMODEL) / (256 * 4), 256>>>(x, xr);

    // QKV fused projection: [8192,1024] @ [1024,3072] -> g_qkv [8192][3072]
    gemm_mma<<<dim3(3072 / 128, ROWS / 128), 256, GEMM_SMEM_BYTES>>>(
        xr, bt, qkv, nullptr, ROWS, 3072, DMODEL, DMODEL, DMODEL, QKV_LD);

    attn_kernel<<<dim3(SEQ / 128, BATCH * NHEADS), 256, ATT_SMEM_BYTES>>>(qkv, ctx);

    // output projection + bias
    gemm_mma<<<dim3(DMODEL / 128, ROWS / 128), 256, GEMM_SMEM_BYTES>>>(
        ctx, wot, out, bo, ROWS, DMODEL, DMODEL, DMODEL, DMODEL, DMODEL);
}

// round 5
// speedup vs baseline: 2.2611x; 1.0258x over previous
#include <cuda_runtime.h>
#include <cuda_bf16.h>
#include <cstdint>
#include <math.h>

// =====================================================================
// helpers
// =====================================================================
__device__ __forceinline__ uint32_t smem_to_u32(const void* smem_ptr) {
    uint32_t addr;
    asm("{ .reg .u64 tmp; cvta.to.shared.u64 tmp, %1; cvt.u32.u64 %0, tmp; }"
        : "=r"(addr) : "l"(smem_ptr));
    return addr;
}
__device__ __forceinline__ uint32_t f2tf32(float f) {
    uint32_t r; asm("cvt.rna.tf32.f32 %0, %1;" : "=r"(r) : "f"(f)); return r;
}
// D += A(16x8) * B(8x8), tf32 inputs (b32 regs), fp32 accumulate
__device__ __forceinline__ void mma_tf32(float* d, const uint32_t* a, const uint32_t* b) {
    asm volatile(
        "mma.sync.aligned.m16n8k8.row.col.f32.tf32.tf32.f32 "
        "{%0,%1,%2,%3}, {%4,%5,%6,%7}, {%8,%9}, {%0,%1,%2,%3};"
        : "+f"(d[0]), "+f"(d[1]), "+f"(d[2]), "+f"(d[3])
        : "r"(a[0]), "r"(a[1]), "r"(a[2]), "r"(a[3]), "r"(b[0]), "r"(b[1]));
}
#define CP_ASYNC16(dst, src) \
    asm volatile("cp.async.cg.shared.global [%0], [%1], 16;" \
                 :: "r"(dst), "l"(src) : "memory")
#define CP_COMMIT() asm volatile("cp.async.commit_group;" ::: "memory")
#define CP_WAIT(n)  asm volatile("cp.async.wait_group %0;" :: "n"(n) : "memory")

// ---------------- problem constants ----------------
#define BATCH 4
#define SEQ   2048
#define DMODEL 1024
#define NHEADS 16
#define HDIM  64
#define ROWS  (BATCH * SEQ)          // 8192
#define QKV_LD 3072

// scratch (device globals: allocation-free per harness rules)
__device__ float g_qkv[(size_t)ROWS * QKV_LD];    // [row][3072]: Q | K | V
__device__ float g_ctx[(size_t)ROWS * DMODEL];    // attention output (tf32-rounded)
__device__ float g_bt[(size_t)3072 * DMODEL];     // [Wq^T; Wk^T; Wv^T] (N,K), tf32-rounded
__device__ float g_wot[(size_t)DMODEL * DMODEL];  // Wo^T (N,K), tf32-rounded
__device__ float g_xr[(size_t)ROWS * DMODEL];     // x, tf32-rounded

// =====================================================================
// transpose + tf32-round: dst[c][r] = round(src[r][c]), 1024x1024
// =====================================================================
__global__ void transpose_1024(const float* __restrict__ src, float* __restrict__ dst)
{
    __shared__ float tile[32][33];
    int x = blockIdx.x * 32 + threadIdx.x;
    int y = blockIdx.y * 32 + threadIdx.y;
    #pragma unroll
    for (int i = 0; i < 32; i += 8)
        tile[threadIdx.y + i][threadIdx.x] = src[(size_t)(y + i) * 1024 + x];
    __syncthreads();
    x = blockIdx.y * 32 + threadIdx.x;
    y = blockIdx.x * 32 + threadIdx.y;
    #pragma unroll
    for (int i = 0; i < 32; i += 8)
        dst[(size_t)(y + i) * 1024 + x] =
            __uint_as_float(f2tf32(tile[threadIdx.x][threadIdx.y + i]));
}

// elementwise tf32 round (for activation matrix)
__global__ void round_tf32(const float* __restrict__ src, float* __restrict__ dst)
{
    size_t i = ((size_t)blockIdx.x * blockDim.x + threadIdx.x) * 4;
    float4 v = *(const float4*)(src + i);
    v.x = __uint_as_float(f2tf32(v.x));
    v.y = __uint_as_float(f2tf32(v.y));
    v.z = __uint_as_float(f2tf32(v.z));
    v.w = __uint_as_float(f2tf32(v.w));
    *(float4*)(dst + i) = v;
}

// =====================================================================
// tf32 mma.sync GEMM: C[M,N] = A[M,K] @ Bt[N,K]^T (+ bias)   (unchanged)
// =====================================================================
#define G_STR 36
#define G_STAGE (128 * G_STR)
#define GEMM_SMEM_BYTES (3 * 2 * G_STAGE * 4)   // 110592

__global__ __launch_bounds__(256, 1)
void gemm_mma(const float* __restrict__ A, const float* __restrict__ Bt,
              float* __restrict__ C, const float* __restrict__ bias,
              int M, int N, int K, int lda, int ldb, int ldc)
{
    extern __shared__ uint32_t smg[];
    const int tid = threadIdx.x, lane = tid & 31, wid = tid >> 5;
    const int warpM = wid >> 1, warpN = wid & 1;
    const int m0 = blockIdx.y << 7, n0 = blockIdx.x << 7;
    uint32_t* As = smg;
    uint32_t* Bs = smg + 3 * G_STAGE;

    const int lr = tid >> 1;
    const int lc = (tid & 1) << 4;
    const float* Ag = A  + (size_t)(m0 + lr) * lda + lc;
    const float* Bg = Bt + (size_t)(n0 + lr) * ldb + lc;
    const uint32_t a_sm = smem_to_u32(As) + (uint32_t)(lr * G_STR + lc) * 4u;
    const uint32_t b_sm = smem_to_u32(Bs) + (uint32_t)(lr * G_STR + lc) * 4u;
    const int nch = K >> 5;

    auto load_stage = [&](int t) {
        const uint32_t off = (uint32_t)(t % 3) * G_STAGE * 4u;
        const float* ag = Ag + t * 32;
        const float* bg = Bg + t * 32;
        #pragma unroll
        for (int i = 0; i < 4; ++i) CP_ASYNC16(a_sm + off + i * 16, ag + i * 4);
        #pragma unroll
        for (int i = 0; i < 4; ++i) CP_ASYNC16(b_sm + off + i * 16, bg + i * 4);
        CP_COMMIT();
    };

    float acc[2][8][4];
    #pragma unroll
    for (int mt = 0; mt < 2; ++mt)
        #pragma unroll
        for (int nt = 0; nt < 8; ++nt)
            #pragma unroll
            for (int j = 0; j < 4; ++j) acc[mt][nt][j] = 0.0f;

    load_stage(0); load_stage(1); load_stage(2);

    const int r0 = lane >> 2, c0 = lane & 3;
    for (int t = 0; t < nch; ++t) {
        CP_WAIT(2);
        __syncthreads();
        const uint32_t* Ab = As + (t % 3) * G_STAGE;
        const uint32_t* Bb = Bs + (t % 3) * G_STAGE;
        #pragma unroll
        for (int ks = 0; ks < 4; ++ks) {
            const int kk = ks * 8 + c0;
            uint32_t af[2][4];
            #pragma unroll
            for (int mt = 0; mt < 2; ++mt) {
                const int mr = warpM * 32 + mt * 16 + r0;
                af[mt][0] = Ab[mr * G_STR + kk];
                af[mt][1] = Ab[(mr + 8) * G_STR + kk];
                af[mt][2] = Ab[mr * G_STR + kk + 4];
                af[mt][3] = Ab[(mr + 8) * G_STR + kk + 4];
            }
            #pragma unroll
            for (int nt = 0; nt < 8; ++nt) {
                const int nr = warpN * 64 + nt * 8 + r0;
                uint32_t bf[2];
                bf[0] = Bb[nr * G_STR + kk];
                bf[1] = Bb[nr * G_STR + kk + 4];
                mma_tf32(acc[0][nt], af[0], bf);
                mma_tf32(acc[1][nt], af[1], bf);
            }
        }
        __syncthreads();
        if (t + 3 < nch) load_stage(t + 3);
    }

    #pragma unroll
    for (int mt = 0; mt < 2; ++mt) {
        const int row = m0 + warpM * 32 + mt * 16 + r0;
        #pragma unroll
        for (int nt = 0; nt < 8; ++nt) {
            const int col = n0 + warpN * 64 + nt * 8 + 2 * c0;
            float b0v = 0.0f, b1v = 0.0f;
            if (bias) { b0v = bias[col]; b1v = bias[col + 1]; }
            *(float2*)(C + (size_t)row * ldc + col) =
                make_float2(acc[mt][nt][0] + b0v, acc[mt][nt][1] + b1v);
            *(float2*)(C + (size_t)(row + 8) * ldc + col) =
                make_float2(acc[mt][nt][2] + b0v, acc[mt][nt][3] + b1v);
        }
    }
}

// =====================================================================
// Flash attention v3 (causal), tf32 mma.sync.
// 128 q per block, 64 kv per tile, 8 warps (16 q each).
// Q fragments in registers; K/V in fragment-major smem, double-buffered
// with register prefetch (LDG at loop top, STS after PV, 1 sync/tile).
//   KF/VF slot (ks, nt, lane) -> 2 u32:
//     KF: { K[nt*8+r0][ks*8+c0], K[nt*8+r0][ks*8+c0+4] }
//     VF: { V[ks*8+c0][nt*8+r0], V[ks*8+c0+4][nt*8+r0] }
//   (warp w gathers the ks=w slice of both)
// =====================================================================
#define AP_STR 68
#define FRAG_U32 4096                          // 8*8*32*2
#define ATT_SMEM_U32 (2*FRAG_U32 + 2*FRAG_U32 + 128*AP_STR)
#define ATT_SMEM_BYTES (ATT_SMEM_U32 * 4)      // 100352

__global__ __launch_bounds__(256, 1)
void attn_kernel(const float* __restrict__ qkv, float* __restrict__ ctx)
{
    extern __shared__ uint32_t sma[];
    uint32_t* KF = sma;                    // [2][8][8][32][2]
    uint32_t* VF = KF + 2 * FRAG_U32;      // [2][8][8][32][2]
    uint32_t* Ps = VF + 2 * FRAG_U32;      // [128][68]

    const int tid = threadIdx.x, lane = tid & 31, wid = tid >> 5;
    const int q0 = blockIdx.x << 7;
    const int bh = blockIdx.y;
    const int bb = bh >> 4, hh = bh & 15;
    const int r0 = lane >> 2, c0 = lane & 3;
    const int q0w = wid << 4;

    const float* qbase = qkv + (size_t)bb * SEQ * QKV_LD + hh * HDIM;
    const float* kbase = qbase + 1024;
    const float* vbase = qbase + 2048;

    // ---- Q fragments into registers ----
    uint32_t qf[8][4];
    {
        const float* qr0 = qbase + (size_t)(q0 + q0w + r0) * QKV_LD;
        const float* qr1 = qr0 + (size_t)8 * QKV_LD;
        #pragma unroll
        for (int ks = 0; ks < 8; ++ks) {
            const int cA = ks * 8 + c0;
            qf[ks][0] = f2tf32(qr0[cA]);
            qf[ks][1] = f2tf32(qr1[cA]);
            qf[ks][2] = f2tf32(qr0[cA + 4]);
            qf[ks][3] = f2tf32(qr1[cA + 4]);
        }
    }

    float krA[8], krB[8], vrA[8], vrB[8];
    // gather tile starting at kv row j0 into registers (warp w -> ks=w slice)
    auto gather = [&](int j0) {
        const float* kb = kbase + (size_t)j0 * QKV_LD;
        const float* vb = vbase + (size_t)j0 * QKV_LD;
        const int kc = wid * 8 + c0;
        #pragma unroll
        for (int nt = 0; nt < 8; ++nt) {
            const float* krow = kb + (size_t)(nt * 8 + r0) * QKV_LD;
            krA[nt] = krow[kc];
            krB[nt] = krow[kc + 4];
            vrA[nt] = vb[(size_t)kc * QKV_LD + nt * 8 + r0];
            vrB[nt] = vb[(size_t)(kc + 4) * QKV_LD + nt * 8 + r0];
        }
    };
    auto commit = [&](int buf) {
        #pragma unroll
        for (int nt = 0; nt < 8; ++nt) {
            const uint32_t slot = (uint32_t)(((wid * 8 + nt) * 32 + lane) * 2);
            uint32_t* kd = KF + buf * FRAG_U32 + slot;
            kd[0] = f2tf32(krA[nt]); kd[1] = f2tf32(krB[nt]);
            uint32_t* vd = VF + buf * FRAG_U32 + slot;
            vd[0] = f2tf32(vrA[nt]); vd[1] = f2tf32(vrB[nt]);
        }
    };

    float m_i[2] = {-1e30f, -1e30f}, l_i[2] = {0.0f, 0.0f};
    float oacc[8][4];
    #pragma unroll
    for (int nt = 0; nt < 8; ++nt)
        #pragma unroll
        for (int j = 0; j < 4; ++j) oacc[nt][j] = 0.0f;

    const float SCL = 0.125f * 1.4426950408889634f;
    const int ntiles = (q0 >> 6) + 2;

    gather(0); commit(0);
    __syncthreads();

    for (int t = 0; t < ntiles; ++t) {
        const int j0 = t << 6;
        const int buf = t & 1;
        if (t + 1 < ntiles) gather(j0 + 64);   // LDGs in flight over compute

        // ---- S = Q K^T ----
        float sacc[8][4];
        #pragma unroll
        for (int nt = 0; nt < 8; ++nt)
            #pragma unroll
            for (int j = 0; j < 4; ++j) sacc[nt][j] = 0.0f;

        const uint32_t* KB = KF + buf * FRAG_U32;
        #pragma unroll
        for (int ks = 0; ks < 8; ++ks) {
            #pragma unroll
            for (int nt = 0; nt < 8; ++nt) {
                uint2 b2 = *(const uint2*)(KB + ((ks * 8 + nt) * 32 + lane) * 2);
                uint32_t bf[2] = {b2.x, b2.y};
                mma_tf32(sacc[nt], qf[ks], bf);
            }
        }

        // ---- online softmax (2 rows per thread) ----
        const bool need_mask = (t >= ntiles - 2);
        float corr[2];
        #pragma unroll
        for (int h = 0; h < 2; ++h) {
            const int grow = q0 + q0w + r0 + h * 8;
            float u[8][2];
            float rmax = -1e30f;
            #pragma unroll
            for (int nt = 0; nt < 8; ++nt) {
                float v0 = sacc[nt][h * 2 + 0] * SCL;
                float v1 = sacc[nt][h * 2 + 1] * SCL;
                if (need_mask) {
                    const int gc = j0 + nt * 8 + 2 * c0;
                    if (gc > grow)     v0 = -1e30f;
                    if (gc + 1 > grow) v1 = -1e30f;
                }
                u[nt][0] = v0; u[nt][1] = v1;
                rmax = fmaxf(rmax, fmaxf(v0, v1));
            }
            rmax = fmaxf(rmax, __shfl_xor_sync(0xffffffffu, rmax, 1));
            rmax = fmaxf(rmax, __shfl_xor_sync(0xffffffffu, rmax, 2));
            const float mn = fmaxf(m_i[h], rmax);
            const float c = exp2f(m_i[h] - mn);
            float psum = 0.0f;
            #pragma unroll
            for (int nt = 0; nt < 8; ++nt) {
                const float p0 = exp2f(u[nt][0] - mn);
                const float p1 = exp2f(u[nt][1] - mn);
                psum += p0 + p1;
                uint32_t* dst = &Ps[(q0w + r0 + h * 8) * AP_STR + nt * 8 + 2 * c0];
                dst[0] = f2tf32(p0); dst[1] = f2tf32(p1);
            }
            psum += __shfl_xor_sync(0xffffffffu, psum, 1);
            psum += __shfl_xor_sync(0xffffffffu, psum, 2);
            l_i[h] = l_i[h] * c + psum;
            m_i[h] = mn;
            corr[h] = c;
        }
        __syncwarp();   // this warp's Ps rows visible to all its lanes

        // rescale O accumulators
        #pragma unroll
        for (int nt = 0; nt < 8; ++nt) {
            oacc[nt][0] *= corr[0]; oacc[nt][1] *= corr[0];
            oacc[nt][2] *= corr[1]; oacc[nt][3] *= corr[1];
        }

        // ---- O += P V ----
        const uint32_t* VB = VF + buf * FRAG_U32;
        #pragma unroll
        for (int ks = 0; ks < 8; ++ks) {
            const int kk = ks * 8 + c0;
            uint32_t af[4];
            af[0] = Ps[(q0w + r0) * AP_STR + kk];
            af[1] = Ps[(q0w + r0 + 8) * AP_STR + kk];
            af[2] = Ps[(q0w + r0) * AP_STR + kk + 4];
            af[3] = Ps[(q0w + r0 + 8) * AP_STR + kk + 4];
            #pragma unroll
            for (int nt = 0; nt < 8; ++nt) {
                uint2 b2 = *(const uint2*)(VB + ((ks * 8 + nt) * 32 + lane) * 2);
                uint32_t bf[2] = {b2.x, b2.y};
                mma_tf32(oacc[nt], af, bf);
            }
        }

        if (t + 1 < ntiles) commit(buf ^ 1);
        __syncthreads();
    }

    // epilogue: ctx (tf32-rounded for next GEMM)
    float* obase = ctx + (size_t)(bb * SEQ + q0 + q0w) * DMODEL + hh * HDIM;
    const float inv0 = 1.0f / l_i[0];
    const float inv1 = 1.0f / l_i[1];
    #pragma unroll
    for (int nt = 0; nt < 8; ++nt) {
        const int col = nt * 8 + 2 * c0;
        float2 w0 = make_float2(
            __uint_as_float(f2tf32(oacc[nt][0] * inv0)),
            __uint_as_float(f2tf32(oacc[nt][1] * inv0)));
        float2 w1 = make_float2(
            __uint_as_float(f2tf32(oacc[nt][2] * inv1)),
            __uint_as_float(f2tf32(oacc[nt][3] * inv1)));
        *(float2*)(obase + (size_t)r0 * DMODEL + col) = w0;
        *(float2*)(obase + (size_t)(r0 + 8) * DMODEL + col) = w1;
    }
}

// =====================================================================
extern "C" void kernel_launch(void* const* d_in, const int* in_sizes, int n_in,
                              void* d_out, int out_size)
{
    const float* x  = (const float*)d_in[0];
    const float* Wq = (const float*)d_in[1];
    const float* Wk = (const float*)d_in[2];
    const float* Wv = (const float*)d_in[3];
    const float* Wo = (const float*)d_in[4];
    const float* bo = (const float*)d_in[5];
    float* out = (float*)d_out;

    float *qkv = nullptr, *ctx = nullptr, *bt = nullptr, *wot = nullptr, *xr = nullptr;
    cudaGetSymbolAddress((void**)&qkv, g_qkv);
    cudaGetSymbolAddress((void**)&ctx, g_ctx);
    cudaGetSymbolAddress((void**)&bt,  g_bt);
    cudaGetSymbolAddress((void**)&wot, g_wot);
    cudaGetSymbolAddress((void**)&xr,  g_xr);
    cudaFuncSetAttribute(attn_kernel,
                         cudaFuncAttributeMaxDynamicSharedMemorySize, ATT_SMEM_BYTES);
    cudaFuncSetAttribute(gemm_mma,
                         cudaFuncAttributeMaxDynamicSharedMemorySize, GEMM_SMEM_BYTES);

    dim3 tb(32, 8), tg(32, 32);
    transpose_1024<<<tg, tb>>>(Wq, bt + 0 * 1024 * 1024);
    transpose_1024<<<tg, tb>>>(Wk, bt + 1 * 1024 * 1024);
    transpose_1024<<<tg, tb>>>(Wv, bt + 2 * 1024 * 1024);
    transpose_1024<<<tg, tb>>>(Wo, wot);
    round_tf32<<<(ROWS * DMODEL) / (256 * 4), 256>>>(x, xr);

    // QKV fused projection: [8192,1024] @ [1024,3072] -> g_qkv [8192][3072]
    gemm_mma<<<dim3(3072 / 128, ROWS / 128), 256, GEMM_SMEM_BYTES>>>(
        xr, bt, qkv, nullptr, ROWS, 3072, DMODEL, DMODEL, DMODEL, QKV_LD);

    attn_kernel<<<dim3(SEQ / 128, BATCH * NHEADS), 256, ATT_SMEM_BYTES>>>(qkv, ctx);

    // output projection + bias
    gemm_mma<<<dim3(DMODEL / 128, ROWS / 128), 256, GEMM_SMEM_BYTES>>>(
        ctx, wot, out, bo, ROWS, DMODEL, DMODEL, DMODEL, DMODEL, DMODEL);
}

// round 6
// speedup vs baseline: 2.7658x; 1.2232x over previous
#include <cuda_runtime.h>
#include <cuda_bf16.h>
#include <cstdint>
#include <math.h>

// =====================================================================
// helpers
// =====================================================================
__device__ __forceinline__ uint32_t smem_to_u32(const void* smem_ptr) {
    uint32_t addr;
    asm("{ .reg .u64 tmp; cvta.to.shared.u64 tmp, %1; cvt.u32.u64 %0, tmp; }"
        : "=r"(addr) : "l"(smem_ptr));
    return addr;
}
__device__ __forceinline__ uint32_t f2tf32(float f) {
    uint32_t r; asm("cvt.rna.tf32.f32 %0, %1;" : "=r"(r) : "f"(f)); return r;
}
// D += A(16x8) * B(8x8), tf32 inputs (b32 regs), fp32 accumulate
__device__ __forceinline__ void mma_tf32(float* d, const uint32_t* a, const uint32_t* b) {
    asm volatile(
        "mma.sync.aligned.m16n8k8.row.col.f32.tf32.tf32.f32 "
        "{%0,%1,%2,%3}, {%4,%5,%6,%7}, {%8,%9}, {%0,%1,%2,%3};"
        : "+f"(d[0]), "+f"(d[1]), "+f"(d[2]), "+f"(d[3])
        : "r"(a[0]), "r"(a[1]), "r"(a[2]), "r"(a[3]), "r"(b[0]), "r"(b[1]));
}
#define CP_ASYNC16(dst, src) \
    asm volatile("cp.async.cg.shared.global [%0], [%1], 16;" \
                 :: "r"(dst), "l"(src) : "memory")
#define CP_COMMIT() asm volatile("cp.async.commit_group;" ::: "memory")
#define CP_WAIT(n)  asm volatile("cp.async.wait_group %0;" :: "n"(n) : "memory")

// ---------------- problem constants ----------------
#define BATCH 4
#define SEQ   2048
#define DMODEL 1024
#define NHEADS 16
#define HDIM  64
#define ROWS  (BATCH * SEQ)          // 8192
#define QKV_LD 3072

// scratch (device globals)
__device__ float    g_qkv[(size_t)ROWS * QKV_LD];     // [row][3072]: Q | K | V
__device__ float    g_ctx[(size_t)ROWS * DMODEL];     // attention output (tf32-rounded)
__device__ float    g_xr[(size_t)ROWS * DMODEL];      // x, tf32-rounded
// fragment-major weights: [nb][kb][lane][2] u32, nb = n/8, kb = k/8
__device__ uint32_t g_btf[(size_t)384 * 128 * 64];    // Wq|Wk|Wv fused (N=3072)
__device__ uint32_t g_wotf[(size_t)128 * 128 * 64];   // Wo (N=1024)

// =====================================================================
// fragify: W[K=1024][N=1024] row-major -> WF[nb][kb][lane][2] (tf32)
//   lane = r0*4 + c0 layout of mma B-fragment:
//   val0 = W[kb*8+c0][nb*8+r0], val1 = W[kb*8+c0+4][nb*8+r0]
// one warp per (nb,kb) slot; 8 slots per 256-thr block; 2048 blocks
// =====================================================================
__global__ void fragify(const float* __restrict__ W, uint32_t* __restrict__ WF)
{
    const int slot = blockIdx.x * 8 + (threadIdx.x >> 5);   // 0..16383
    const int lane = threadIdx.x & 31;
    const int nb = slot >> 7, kb = slot & 127;
    const int r0 = lane >> 2, c0 = lane & 3;
    const float v0 = W[(size_t)(kb * 8 + c0) * 1024 + nb * 8 + r0];
    const float v1 = W[(size_t)(kb * 8 + c0 + 4) * 1024 + nb * 8 + r0];
    uint32_t* dst = WF + ((size_t)slot * 32 + lane) * 2;
    dst[0] = f2tf32(v0);
    dst[1] = f2tf32(v1);
}

// elementwise tf32 round (for activation matrix)
__global__ void round_tf32(const float* __restrict__ src, float* __restrict__ dst)
{
    size_t i = ((size_t)blockIdx.x * blockDim.x + threadIdx.x) * 4;
    float4 v = *(const float4*)(src + i);
    v.x = __uint_as_float(f2tf32(v.x));
    v.y = __uint_as_float(f2tf32(v.y));
    v.z = __uint_as_float(f2tf32(v.z));
    v.w = __uint_as_float(f2tf32(v.w));
    *(float4*)(dst + i) = v;
}

// =====================================================================
// tf32 mma.sync GEMM v2: C[M,N] = A[M,K] @ Wfrag (+ bias)
// 128x128 tile, BK=32, 3-stage cp.async, 256 thr, 2 blocks/SM.
// A row-major (tf32-rounded); B pre-packed fragment-major.
// smem/stage: A 128x36 u32 (18KB) + B [4kb][16nb][32][2] (16KB)
// =====================================================================
#define G_STR 36
#define A_STAGE_U32 (128 * G_STR)       // 4608
#define B_STAGE_U32 (4 * 16 * 64)       // 4096
#define GEMM_SMEM_BYTES (3 * (A_STAGE_U32 + B_STAGE_U32) * 4)   // 104448

__global__ __launch_bounds__(256, 2)
void gemm_mma(const float* __restrict__ A, const uint32_t* __restrict__ WF,
              float* __restrict__ C, const float* __restrict__ bias,
              int M, int N, int K, int lda, int ldc)
{
    extern __shared__ uint32_t smg[];
    const int tid = threadIdx.x, lane = tid & 31, wid = tid >> 5;
    const int warpM = wid >> 1, warpN = wid & 1;
    const int m0 = blockIdx.y << 7, n0 = blockIdx.x << 7;
    uint32_t* As = smg;                         // [3][4608]
    uint32_t* Bs = smg + 3 * A_STAGE_U32;       // [3][4096]

    const int kbN = K >> 3;                     // kb entries per nb row
    // A staging: 2 threads/row, 16 floats each
    const int lr = tid >> 1;
    const int lc = (tid & 1) << 4;
    const float* Ag = A + (size_t)(m0 + lr) * lda + lc;
    const uint32_t a_sm = smem_to_u32(As) + (uint32_t)(lr * G_STR + lc) * 4u;
    // B staging: thread t -> nb_l = t>>4, 16B unit = t&15
    const int nb_l = tid >> 4;
    const int part = tid & 15;
    const uint32_t* Bg = WF + ((size_t)((n0 >> 3) + nb_l) * kbN) * 64 + part * 4;
    const uint32_t b_sm = smem_to_u32(Bs);
    const int nch = K >> 5;

    auto load_stage = [&](int t) {
        const uint32_t aoff = (uint32_t)(t % 3) * A_STAGE_U32 * 4u;
        const float* ag = Ag + t * 32;
        #pragma unroll
        for (int i = 0; i < 4; ++i) CP_ASYNC16(a_sm + aoff + i * 16, ag + i * 4);
        const uint32_t boff = (uint32_t)(t % 3) * B_STAGE_U32 * 4u;
        const uint32_t* bg = Bg + (size_t)(t * 4) * 64;
        #pragma unroll
        for (int kb = 0; kb < 4; ++kb)
            CP_ASYNC16(b_sm + boff + (uint32_t)((kb * 16 + nb_l) * 64 + part * 4) * 4u,
                       bg + (size_t)kb * 64);
        CP_COMMIT();
    };

    float acc[2][8][4];
    #pragma unroll
    for (int mt = 0; mt < 2; ++mt)
        #pragma unroll
        for (int nt = 0; nt < 8; ++nt)
            #pragma unroll
            for (int j = 0; j < 4; ++j) acc[mt][nt][j] = 0.0f;

    load_stage(0); load_stage(1);

    const int r0 = lane >> 2, c0 = lane & 3;
    for (int t = 0; t < nch; ++t) {
        CP_WAIT(1);
        __syncthreads();
        if (t + 2 < nch) load_stage(t + 2);
        const uint32_t* Ab = As + (t % 3) * A_STAGE_U32;
        const uint32_t* Bb = Bs + (t % 3) * B_STAGE_U32;
        #pragma unroll
        for (int ks = 0; ks < 4; ++ks) {
            const int kk = ks * 8 + c0;
            uint32_t af[2][4];
            #pragma unroll
            for (int mt = 0; mt < 2; ++mt) {
                const int mr = warpM * 32 + mt * 16 + r0;
                af[mt][0] = Ab[mr * G_STR + kk];
                af[mt][1] = Ab[(mr + 8) * G_STR + kk];
                af[mt][2] = Ab[mr * G_STR + kk + 4];
                af[mt][3] = Ab[(mr + 8) * G_STR + kk + 4];
            }
            #pragma unroll
            for (int nt = 0; nt < 8; ++nt) {
                uint2 b2 = *(const uint2*)(Bb + ((ks * 16 + warpN * 8 + nt) * 64
                                                 + lane * 2));
                uint32_t bf[2] = {b2.x, b2.y};
                mma_tf32(acc[0][nt], af[0], bf);
                mma_tf32(acc[1][nt], af[1], bf);
            }
        }
    }

    #pragma unroll
    for (int mt = 0; mt < 2; ++mt) {
        const int row = m0 + warpM * 32 + mt * 16 + r0;
        #pragma unroll
        for (int nt = 0; nt < 8; ++nt) {
            const int col = n0 + warpN * 64 + nt * 8 + 2 * c0;
            float b0v = 0.0f, b1v = 0.0f;
            if (bias) { b0v = bias[col]; b1v = bias[col + 1]; }
            *(float2*)(C + (size_t)row * ldc + col) =
                make_float2(acc[mt][nt][0] + b0v, acc[mt][nt][1] + b1v);
            *(float2*)(C + (size_t)(row + 8) * ldc + col) =
                make_float2(acc[mt][nt][2] + b0v, acc[mt][nt][3] + b1v);
        }
    }
}

// =====================================================================
// Flash attention v3 (causal), tf32 mma.sync.  (unchanged from R5)
// =====================================================================
#define AP_STR 68
#define FRAG_U32 4096
#define ATT_SMEM_U32 (2*FRAG_U32 + 2*FRAG_U32 + 128*AP_STR)
#define ATT_SMEM_BYTES (ATT_SMEM_U32 * 4)      // 100352

__global__ __launch_bounds__(256, 1)
void attn_kernel(const float* __restrict__ qkv, float* __restrict__ ctx)
{
    extern __shared__ uint32_t sma[];
    uint32_t* KF = sma;
    uint32_t* VF = KF + 2 * FRAG_U32;
    uint32_t* Ps = VF + 2 * FRAG_U32;

    const int tid = threadIdx.x, lane = tid & 31, wid = tid >> 5;
    const int q0 = blockIdx.x << 7;
    const int bh = blockIdx.y;
    const int bb = bh >> 4, hh = bh & 15;
    const int r0 = lane >> 2, c0 = lane & 3;
    const int q0w = wid << 4;

    const float* qbase = qkv + (size_t)bb * SEQ * QKV_LD + hh * HDIM;
    const float* kbase = qbase + 1024;
    const float* vbase = qbase + 2048;

    uint32_t qf[8][4];
    {
        const float* qr0 = qbase + (size_t)(q0 + q0w + r0) * QKV_LD;
        const float* qr1 = qr0 + (size_t)8 * QKV_LD;
        #pragma unroll
        for (int ks = 0; ks < 8; ++ks) {
            const int cA = ks * 8 + c0;
            qf[ks][0] = f2tf32(qr0[cA]);
            qf[ks][1] = f2tf32(qr1[cA]);
            qf[ks][2] = f2tf32(qr0[cA + 4]);
            qf[ks][3] = f2tf32(qr1[cA + 4]);
        }
    }

    float krA[8], krB[8], vrA[8], vrB[8];
    auto gather = [&](int j0) {
        const float* kb = kbase + (size_t)j0 * QKV_LD;
        const float* vb = vbase + (size_t)j0 * QKV_LD;
        const int kc = wid * 8 + c0;
        #pragma unroll
        for (int nt = 0; nt < 8; ++nt) {
            const float* krow = kb + (size_t)(nt * 8 + r0) * QKV_LD;
            krA[nt] = krow[kc];
            krB[nt] = krow[kc + 4];
            vrA[nt] = vb[(size_t)kc * QKV_LD + nt * 8 + r0];
            vrB[nt] = vb[(size_t)(kc + 4) * QKV_LD + nt * 8 + r0];
        }
    };
    auto commit = [&](int buf) {
        #pragma unroll
        for (int nt = 0; nt < 8; ++nt) {
            const uint32_t slot = (uint32_t)(((wid * 8 + nt) * 32 + lane) * 2);
            uint32_t* kd = KF + buf * FRAG_U32 + slot;
            kd[0] = f2tf32(krA[nt]); kd[1] = f2tf32(krB[nt]);
            uint32_t* vd = VF + buf * FRAG_U32 + slot;
            vd[0] = f2tf32(vrA[nt]); vd[1] = f2tf32(vrB[nt]);
        }
    };

    float m_i[2] = {-1e30f, -1e30f}, l_i[2] = {0.0f, 0.0f};
    float oacc[8][4];
    #pragma unroll
    for (int nt = 0; nt < 8; ++nt)
        #pragma unroll
        for (int j = 0; j < 4; ++j) oacc[nt][j] = 0.0f;

    const float SCL = 0.125f * 1.4426950408889634f;
    const int ntiles = (q0 >> 6) + 2;

    gather(0); commit(0);
    __syncthreads();

    for (int t = 0; t < ntiles; ++t) {
        const int j0 = t << 6;
        const int buf = t & 1;
        if (t + 1 < ntiles) gather(j0 + 64);

        float sacc[8][4];
        #pragma unroll
        for (int nt = 0; nt < 8; ++nt)
            #pragma unroll
            for (int j = 0; j < 4; ++j) sacc[nt][j] = 0.0f;

        const uint32_t* KB = KF + buf * FRAG_U32;
        #pragma unroll
        for (int ks = 0; ks < 8; ++ks) {
            #pragma unroll
            for (int nt = 0; nt < 8; ++nt) {
                uint2 b2 = *(const uint2*)(KB + ((ks * 8 + nt) * 32 + lane) * 2);
                uint32_t bf[2] = {b2.x, b2.y};
                mma_tf32(sacc[nt], qf[ks], bf);
            }
        }

        const bool need_mask = (t >= ntiles - 2);
        float corr[2];
        #pragma unroll
        for (int h = 0; h < 2; ++h) {
            const int grow = q0 + q0w + r0 + h * 8;
            float u[8][2];
            float rmax = -1e30f;
            #pragma unroll
            for (int nt = 0; nt < 8; ++nt) {
                float v0 = sacc[nt][h * 2 + 0] * SCL;
                float v1 = sacc[nt][h * 2 + 1] * SCL;
                if (need_mask) {
                    const int gc = j0 + nt * 8 + 2 * c0;
                    if (gc > grow)     v0 = -1e30f;
                    if (gc + 1 > grow) v1 = -1e30f;
                }
                u[nt][0] = v0; u[nt][1] = v1;
                rmax = fmaxf(rmax, fmaxf(v0, v1));
            }
            rmax = fmaxf(rmax, __shfl_xor_sync(0xffffffffu, rmax, 1));
            rmax = fmaxf(rmax, __shfl_xor_sync(0xffffffffu, rmax, 2));
            const float mn = fmaxf(m_i[h], rmax);
            const float c = exp2f(m_i[h] - mn);
            float psum = 0.0f;
            #pragma unroll
            for (int nt = 0; nt < 8; ++nt) {
                const float p0 = exp2f(u[nt][0] - mn);
                const float p1 = exp2f(u[nt][1] - mn);
                psum += p0 + p1;
                uint32_t* dst = &Ps[(q0w + r0 + h * 8) * AP_STR + nt * 8 + 2 * c0];
                dst[0] = f2tf32(p0); dst[1] = f2tf32(p1);
            }
            psum += __shfl_xor_sync(0xffffffffu, psum, 1);
            psum += __shfl_xor_sync(0xffffffffu, psum, 2);
            l_i[h] = l_i[h] * c + psum;
            m_i[h] = mn;
            corr[h] = c;
        }
        __syncwarp();

        #pragma unroll
        for (int nt = 0; nt < 8; ++nt) {
            oacc[nt][0] *= corr[0]; oacc[nt][1] *= corr[0];
            oacc[nt][2] *= corr[1]; oacc[nt][3] *= corr[1];
        }

        const uint32_t* VB = VF + buf * FRAG_U32;
        #pragma unroll
        for (int ks = 0; ks < 8; ++ks) {
            const int kk = ks * 8 + c0;
            uint32_t af[4];
            af[0] = Ps[(q0w + r0) * AP_STR + kk];
            af[1] = Ps[(q0w + r0 + 8) * AP_STR + kk];
            af[2] = Ps[(q0w + r0) * AP_STR + kk + 4];
            af[3] = Ps[(q0w + r0 + 8) * AP_STR + kk + 4];
            #pragma unroll
            for (int nt = 0; nt < 8; ++nt) {
                uint2 b2 = *(const uint2*)(VB + ((ks * 8 + nt) * 32 + lane) * 2);
                uint32_t bf[2] = {b2.x, b2.y};
                mma_tf32(oacc[nt], af, bf);
            }
        }

        if (t + 1 < ntiles) commit(buf ^ 1);
        __syncthreads();
    }

    float* obase = ctx + (size_t)(bb * SEQ + q0 + q0w) * DMODEL + hh * HDIM;
    const float inv0 = 1.0f / l_i[0];
    const float inv1 = 1.0f / l_i[1];
    #pragma unroll
    for (int nt = 0; nt < 8; ++nt) {
        const int col = nt * 8 + 2 * c0;
        float2 w0 = make_float2(
            __uint_as_float(f2tf32(oacc[nt][0] * inv0)),
            __uint_as_float(f2tf32(oacc[nt][1] * inv0)));
        float2 w1 = make_float2(
            __uint_as_float(f2tf32(oacc[nt][2] * inv1)),
            __uint_as_float(f2tf32(oacc[nt][3] * inv1)));
        *(float2*)(obase + (size_t)r0 * DMODEL + col) = w0;
        *(float2*)(obase + (size_t)(r0 + 8) * DMODEL + col) = w1;
    }
}

// =====================================================================
extern "C" void kernel_launch(void* const* d_in, const int* in_sizes, int n_in,
                              void* d_out, int out_size)
{
    const float* x  = (const float*)d_in[0];
    const float* Wq = (const float*)d_in[1];
    const float* Wk = (const float*)d_in[2];
    const float* Wv = (const float*)d_in[3];
    const float* Wo = (const float*)d_in[4];
    const float* bo = (const float*)d_in[5];
    float* out = (float*)d_out;

    float *qkv = nullptr, *ctx = nullptr, *xr = nullptr;
    uint32_t *btf = nullptr, *wotf = nullptr;
    cudaGetSymbolAddress((void**)&qkv,  g_qkv);
    cudaGetSymbolAddress((void**)&ctx,  g_ctx);
    cudaGetSymbolAddress((void**)&xr,   g_xr);
    cudaGetSymbolAddress((void**)&btf,  g_btf);
    cudaGetSymbolAddress((void**)&wotf, g_wotf);
    cudaFuncSetAttribute(attn_kernel,
                         cudaFuncAttributeMaxDynamicSharedMemorySize, ATT_SMEM_BYTES);
    cudaFuncSetAttribute(gemm_mma,
                         cudaFuncAttributeMaxDynamicSharedMemorySize, GEMM_SMEM_BYTES);

    const size_t WF_MAT = (size_t)128 * 128 * 64;   // u32 per 1024x1024 matrix
    fragify<<<2048, 256>>>(Wq, btf + 0 * WF_MAT);
    fragify<<<2048, 256>>>(Wk, btf + 1 * WF_MAT);
    fragify<<<2048, 256>>>(Wv, btf + 2 * WF_MAT);
    fragify<<<2048, 256>>>(Wo, wotf);
    round_tf32<<<(ROWS * DMODEL) / (256 * 4), 256>>>(x, xr);

    // QKV fused projection: [8192,1024] @ fused W -> g_qkv [8192][3072]
    gemm_mma<<<dim3(3072 / 128, ROWS / 128), 256, GEMM_SMEM_BYTES>>>(
        xr, btf, qkv, nullptr, ROWS, 3072, DMODEL, DMODEL, QKV_LD);

    attn_kernel<<<dim3(SEQ / 128, BATCH * NHEADS), 256, ATT_SMEM_BYTES>>>(qkv, ctx);

    // output projection + bias
    gemm_mma<<<dim3(DMODEL / 128, ROWS / 128), 256, GEMM_SMEM_BYTES>>>(
        ctx, wotf, out, bo, ROWS, DMODEL, DMODEL, DMODEL, DMODEL);
}

// round 7
// speedup vs baseline: 4.8507x; 1.7538x over previous
#include <cuda_runtime.h>
#include <cuda_fp16.h>
#include <cstdint>
#include <math.h>

// =====================================================================
// helpers
// =====================================================================
__device__ __forceinline__ uint32_t smem_to_u32(const void* smem_ptr) {
    uint32_t addr;
    asm("{ .reg .u64 tmp; cvta.to.shared.u64 tmp, %1; cvt.u32.u64 %0, tmp; }"
        : "=r"(addr) : "l"(smem_ptr));
    return addr;
}
__device__ __forceinline__ uint32_t pack_h2(float x, float y) {
    __half2 h = __floats2half2_rn(x, y);
    return *reinterpret_cast<uint32_t*>(&h);
}
// D += A(16x16) * B(16x8), fp16 inputs, fp32 accumulate
__device__ __forceinline__ void mma_f16(float* d, const uint32_t* a, const uint32_t* b) {
    asm volatile(
        "mma.sync.aligned.m16n8k16.row.col.f32.f16.f16.f32 "
        "{%0,%1,%2,%3}, {%4,%5,%6,%7}, {%8,%9}, {%0,%1,%2,%3};"
        : "+f"(d[0]), "+f"(d[1]), "+f"(d[2]), "+f"(d[3])
        : "r"(a[0]), "r"(a[1]), "r"(a[2]), "r"(a[3]), "r"(b[0]), "r"(b[1]));
}
#define CP_ASYNC16(dst, src) \
    asm volatile("cp.async.cg.shared.global [%0], [%1], 16;" \
                 :: "r"(dst), "l"(src) : "memory")
#define CP_COMMIT() asm volatile("cp.async.commit_group;" ::: "memory")
#define CP_WAIT(n)  asm volatile("cp.async.wait_group %0;" :: "n"(n) : "memory")

// ---------------- problem constants ----------------
#define BATCH 4
#define SEQ   2048
#define DMODEL 1024
#define NHEADS 16
#define HDIM  64
#define ROWS  (BATCH * SEQ)          // 8192
#define QKV_LD 3072

// scratch (device globals)
__device__ float    g_qkv[(size_t)ROWS * QKV_LD];     // [row][3072]: Q | K | V (fp32)
__device__ __half   g_xh[(size_t)ROWS * DMODEL];      // x as fp16
__device__ __half   g_ctxh[(size_t)ROWS * DMODEL];    // attention output as fp16
// fragment-major fp16 weights: [nb][kb16][lane][2] u32 (each u32 = half2)
__device__ uint32_t g_btf[(size_t)384 * 64 * 64];     // Wq|Wk|Wv fused (N=3072)
__device__ uint32_t g_wotf[(size_t)128 * 64 * 64];    // Wo (N=1024)

// =====================================================================
// fragify_h: W[K=1024][N=1024] row-major -> fp16 B-fragments (m16n8k16)
//   slot (nb, kb16); lane (r0=lane>>2, c0=lane&3):
//   reg0 = half2(W[kb*16+2c0][nb*8+r0], W[kb*16+2c0+1][...])
//   reg1 = half2(W[kb*16+2c0+8][...],   W[kb*16+2c0+9][...])
// =====================================================================
__global__ void fragify_h(const float* __restrict__ W, uint32_t* __restrict__ WF)
{
    const int slot = blockIdx.x * 8 + (threadIdx.x >> 5);   // 0..8191
    const int lane = threadIdx.x & 31;
    const int nb = slot >> 6, kb = slot & 63;
    const int r0 = lane >> 2, c0 = lane & 3;
    const int row = kb * 16 + c0 * 2, col = nb * 8 + r0;
    uint32_t b0 = pack_h2(W[(size_t)row * 1024 + col],
                          W[(size_t)(row + 1) * 1024 + col]);
    uint32_t b1 = pack_h2(W[(size_t)(row + 8) * 1024 + col],
                          W[(size_t)(row + 9) * 1024 + col]);
    uint32_t* dst = WF + (size_t)slot * 64 + lane * 2;
    dst[0] = b0; dst[1] = b1;
}

// fp32 -> fp16 elementwise
__global__ void to_half(const float* __restrict__ src, __half* __restrict__ dst)
{
    size_t i = ((size_t)blockIdx.x * blockDim.x + threadIdx.x) * 4;
    float4 v = *(const float4*)(src + i);
    uint2 o;
    o.x = pack_h2(v.x, v.y);
    o.y = pack_h2(v.z, v.w);
    *(uint2*)(dst + i) = o;
}

// =====================================================================
// fp16 mma.sync GEMM: C[M,N](fp32) = A[M,K](fp16) @ Wfrag (+ bias)
// 128x128 tile, BK=32 (2 K16-steps), 3-stage cp.async, 256 thr, 2 blk/SM
// smem/stage: A 128 rows x 40 halves (10KB) + B [2][16][64]u32 (8KB)
// =====================================================================
#define GA_STR32 20                        // u32 per A smem row (40 halves)
#define GA_STAGE_U32 (128 * GA_STR32)      // 2560
#define GB_STAGE_U32 (2 * 16 * 64)         // 2048
#define G_STAGE_U32 (GA_STAGE_U32 + GB_STAGE_U32)
#define GEMM_SMEM_BYTES (3 * G_STAGE_U32 * 4)   // 55296

__global__ __launch_bounds__(256, 2)
void gemm_mma(const __half* __restrict__ A, const uint32_t* __restrict__ WF,
              float* __restrict__ C, const float* __restrict__ bias,
              int M, int N, int K, int lda, int ldc)
{
    extern __shared__ uint32_t smg[];
    const int tid = threadIdx.x, lane = tid & 31, wid = tid >> 5;
    const int warpM = wid >> 1, warpN = wid & 1;
    const int m0 = blockIdx.y << 7, n0 = blockIdx.x << 7;

    const int kbN16 = K >> 4;
    // A staging: 2 threads/row, 16 halves (32B) each
    const int lr = tid >> 1;
    const int lc = (tid & 1) << 4;                  // half offset 0 or 16
    const __half* Ag = A + (size_t)(m0 + lr) * lda + lc;
    const uint32_t smbase = smem_to_u32(smg);
    const uint32_t a_sm = smbase + (uint32_t)(lr * 80 + lc * 2);
    // B staging: nb_l = tid>>4 (0..15), part = tid&15 (16B unit)
    const int nb_l = tid >> 4;
    const int part = tid & 15;
    const uint32_t* Bg = WF + ((size_t)((n0 >> 3) + nb_l) * kbN16) * 64 + part * 4;
    const uint32_t b_sm = smbase + GA_STAGE_U32 * 4 +
                          (uint32_t)((nb_l * 64 + part * 4) * 4);
    const int nch = K >> 5;

    auto load_stage = [&](int t) {
        const uint32_t soff = (uint32_t)(t % 3) * (G_STAGE_U32 * 4u);
        const __half* ag = Ag + t * 32;
        CP_ASYNC16(a_sm + soff, ag);
        CP_ASYNC16(a_sm + soff + 16, ag + 8);
        #pragma unroll
        for (int ks = 0; ks < 2; ++ks)
            CP_ASYNC16(b_sm + soff + (uint32_t)(ks * 16 * 64 * 4),
                       Bg + (size_t)(t * 2 + ks) * 64);
        CP_COMMIT();
    };

    float acc[2][8][4];
    #pragma unroll
    for (int mt = 0; mt < 2; ++mt)
        #pragma unroll
        for (int nt = 0; nt < 8; ++nt)
            #pragma unroll
            for (int j = 0; j < 4; ++j) acc[mt][nt][j] = 0.0f;

    load_stage(0); load_stage(1);

    const int r0 = lane >> 2, c0 = lane & 3;
    for (int t = 0; t < nch; ++t) {
        CP_WAIT(1);
        __syncthreads();
        if (t + 2 < nch) load_stage(t + 2);
        const uint32_t* Ab = smg + (t % 3) * G_STAGE_U32;
        const uint32_t* Bb = Ab + GA_STAGE_U32;
        #pragma unroll
        for (int ks = 0; ks < 2; ++ks) {
            const int kb = ks * 8 + c0;
            uint32_t af[2][4];
            #pragma unroll
            for (int mt = 0; mt < 2; ++mt) {
                const int mr = warpM * 32 + mt * 16 + r0;
                af[mt][0] = Ab[mr * GA_STR32 + kb];
                af[mt][1] = Ab[(mr + 8) * GA_STR32 + kb];
                af[mt][2] = Ab[mr * GA_STR32 + kb + 4];
                af[mt][3] = Ab[(mr + 8) * GA_STR32 + kb + 4];
            }
            #pragma unroll
            for (int nt = 0; nt < 8; ++nt) {
                uint2 b2 = *(const uint2*)(Bb + ((ks * 16 + warpN * 8 + nt) * 64
                                                 + lane * 2));
                uint32_t bf[2] = {b2.x, b2.y};
                mma_f16(acc[0][nt], af[0], bf);
                mma_f16(acc[1][nt], af[1], bf);
            }
        }
    }

    #pragma unroll
    for (int mt = 0; mt < 2; ++mt) {
        const int row = m0 + warpM * 32 + mt * 16 + r0;
        #pragma unroll
        for (int nt = 0; nt < 8; ++nt) {
            const int col = n0 + warpN * 64 + nt * 8 + 2 * c0;
            float b0v = 0.0f, b1v = 0.0f;
            if (bias) { b0v = bias[col]; b1v = bias[col + 1]; }
            *(float2*)(C + (size_t)row * ldc + col) =
                make_float2(acc[mt][nt][0] + b0v, acc[mt][nt][1] + b1v);
            *(float2*)(C + (size_t)(row + 8) * ldc + col) =
                make_float2(acc[mt][nt][2] + b0v, acc[mt][nt][3] + b1v);
        }
    }
}

// =====================================================================
// Flash attention v4 (causal), fp16 mma m16n8k16.
// 128 q per block, 64 kv per tile, 8 warps (16 q each).
// Q fragments in regs; K/V fragment-major smem double-buffered:
//   warps 0-3 gather K slice ks16=w; warps 4-7 gather V slice ks16=w-4.
// P staged as packed half2 (one u32 per fragment element pair).
// =====================================================================
#define AP_STR32 36
#define KV_U32 2048                                   // 4*8*64
#define ATT_SMEM_U32 (2*KV_U32 + 2*KV_U32 + 128*AP_STR32)
#define ATT_SMEM_BYTES (ATT_SMEM_U32 * 4)             // 51200

__global__ __launch_bounds__(256, 1)
void attn_kernel(const float* __restrict__ qkv, __half* __restrict__ ctxh)
{
    extern __shared__ uint32_t sma[];
    uint32_t* KF = sma;                    // [2][4][8][64]
    uint32_t* VF = KF + 2 * KV_U32;        // [2][4][8][64]
    uint32_t* Ps = VF + 2 * KV_U32;        // [128][36] u32 (half2)

    const int tid = threadIdx.x, lane = tid & 31, wid = tid >> 5;
    const int q0 = blockIdx.x << 7;
    const int bh = blockIdx.y;
    const int bb = bh >> 4, hh = bh & 15;
    const int r0 = lane >> 2, c0 = lane & 3;
    const int q0w = wid << 4;

    const float* qbase = qkv + (size_t)bb * SEQ * QKV_LD + hh * HDIM;
    const float* kbase = qbase + 1024;
    const float* vbase = qbase + 2048;

    // ---- Q fragments (4 K16-steps over HDIM=64) ----
    uint32_t qf[4][4];
    {
        const float* qr0 = qbase + (size_t)(q0 + q0w + r0) * QKV_LD;
        const float* qr1 = qr0 + (size_t)8 * QKV_LD;
        #pragma unroll
        for (int ks = 0; ks < 4; ++ks) {
            const int c = ks * 16 + 2 * c0;
            qf[ks][0] = pack_h2(qr0[c], qr0[c + 1]);
            qf[ks][1] = pack_h2(qr1[c], qr1[c + 1]);
            qf[ks][2] = pack_h2(qr0[c + 8], qr0[c + 9]);
            qf[ks][3] = pack_h2(qr1[c + 8], qr1[c + 9]);
        }
    }

    const bool isV = (wid >= 4);
    const int slice = wid & 3;
    float2 gr0[8], gr1[8];
    auto gather = [&](int j0) {
        if (!isV) {
            const float* kb = kbase + (size_t)j0 * QKV_LD;
            const int c = slice * 16 + 2 * c0;
            #pragma unroll
            for (int nt = 0; nt < 8; ++nt) {
                const float* row = kb + (size_t)(nt * 8 + r0) * QKV_LD;
                gr0[nt] = *(const float2*)(row + c);
                gr1[nt] = *(const float2*)(row + c + 8);
            }
        } else {
            const float* vb = vbase + (size_t)j0 * QKV_LD;
            const int rr = slice * 16 + 2 * c0;
            #pragma unroll
            for (int nt = 0; nt < 8; ++nt) {
                const int cc = nt * 8 + r0;
                gr0[nt] = make_float2(vb[(size_t)rr * QKV_LD + cc],
                                      vb[(size_t)(rr + 1) * QKV_LD + cc]);
                gr1[nt] = make_float2(vb[(size_t)(rr + 8) * QKV_LD + cc],
                                      vb[(size_t)(rr + 9) * QKV_LD + cc]);
            }
        }
    };
    auto commit = [&](int buf) {
        uint32_t* base = (isV ? VF : KF) + buf * KV_U32 + slice * 8 * 64;
        #pragma unroll
        for (int nt = 0; nt < 8; ++nt) {
            uint32_t* d = base + nt * 64 + lane * 2;
            d[0] = pack_h2(gr0[nt].x, gr0[nt].y);
            d[1] = pack_h2(gr1[nt].x, gr1[nt].y);
        }
    };

    float m_i[2] = {-1e30f, -1e30f}, l_i[2] = {0.0f, 0.0f};
    float oacc[8][4];
    #pragma unroll
    for (int nt = 0; nt < 8; ++nt)
        #pragma unroll
        for (int j = 0; j < 4; ++j) oacc[nt][j] = 0.0f;

    const float SCL = 0.125f * 1.4426950408889634f;
    const int ntiles = (q0 >> 6) + 2;

    gather(0); commit(0);
    __syncthreads();

    for (int t = 0; t < ntiles; ++t) {
        const int j0 = t << 6;
        const int buf = t & 1;
        if (t + 1 < ntiles) gather(j0 + 64);   // LDGs in flight over compute

        // ---- S = Q K^T ----
        float sacc[8][4];
        #pragma unroll
        for (int nt = 0; nt < 8; ++nt)
            #pragma unroll
            for (int j = 0; j < 4; ++j) sacc[nt][j] = 0.0f;

        const uint32_t* KB = KF + buf * KV_U32;
        #pragma unroll
        for (int ks = 0; ks < 4; ++ks) {
            #pragma unroll
            for (int nt = 0; nt < 8; ++nt) {
                uint2 b2 = *(const uint2*)(KB + ((ks * 8 + nt) * 64 + lane * 2));
                uint32_t bf[2] = {b2.x, b2.y};
                mma_f16(sacc[nt], qf[ks], bf);
            }
        }

        // ---- online softmax (2 rows per thread) ----
        const bool need_mask = (t >= ntiles - 2);
        float corr[2];
        #pragma unroll
        for (int h = 0; h < 2; ++h) {
            const int grow = q0 + q0w + r0 + h * 8;
            float u[8][2];
            float rmax = -1e30f;
            #pragma unroll
            for (int nt = 0; nt < 8; ++nt) {
                float v0 = sacc[nt][h * 2 + 0] * SCL;
                float v1 = sacc[nt][h * 2 + 1] * SCL;
                if (need_mask) {
                    const int gc = j0 + nt * 8 + 2 * c0;
                    if (gc > grow)     v0 = -1e30f;
                    if (gc + 1 > grow) v1 = -1e30f;
                }
                u[nt][0] = v0; u[nt][1] = v1;
                rmax = fmaxf(rmax, fmaxf(v0, v1));
            }
            rmax = fmaxf(rmax, __shfl_xor_sync(0xffffffffu, rmax, 1));
            rmax = fmaxf(rmax, __shfl_xor_sync(0xffffffffu, rmax, 2));
            const float mn = fmaxf(m_i[h], rmax);
            const float c = exp2f(m_i[h] - mn);
            float psum = 0.0f;
            #pragma unroll
            for (int nt = 0; nt < 8; ++nt) {
                const float p0 = exp2f(u[nt][0] - mn);
                const float p1 = exp2f(u[nt][1] - mn);
                psum += p0 + p1;
                Ps[(q0w + r0 + h * 8) * AP_STR32 + nt * 4 + c0] = pack_h2(p0, p1);
            }
            psum += __shfl_xor_sync(0xffffffffu, psum, 1);
            psum += __shfl_xor_sync(0xffffffffu, psum, 2);
            l_i[h] = l_i[h] * c + psum;
            m_i[h] = mn;
            corr[h] = c;
        }
        __syncwarp();   // this warp's Ps rows visible to all its lanes

        // rescale O accumulators
        #pragma unroll
        for (int nt = 0; nt < 8; ++nt) {
            oacc[nt][0] *= corr[0]; oacc[nt][1] *= corr[0];
            oacc[nt][2] *= corr[1]; oacc[nt][3] *= corr[1];
        }

        // ---- O += P V ----
        const uint32_t* VB = VF + buf * KV_U32;
        #pragma unroll
        for (int ks = 0; ks < 4; ++ks) {
            uint32_t af[4];
            af[0] = Ps[(q0w + r0) * AP_STR32 + ks * 8 + c0];
            af[1] = Ps[(q0w + r0 + 8) * AP_STR32 + ks * 8 + c0];
            af[2] = Ps[(q0w + r0) * AP_STR32 + ks * 8 + c0 + 4];
            af[3] = Ps[(q0w + r0 + 8) * AP_STR32 + ks * 8 + c0 + 4];
            #pragma unroll
            for (int nt = 0; nt < 8; ++nt) {
                uint2 b2 = *(const uint2*)(VB + ((ks * 8 + nt) * 64 + lane * 2));
                uint32_t bf[2] = {b2.x, b2.y};
                mma_f16(oacc[nt], af, bf);
            }
        }

        if (t + 1 < ntiles) commit(buf ^ 1);
        __syncthreads();
    }

    // epilogue: ctx as fp16 (feeds output GEMM directly)
    __half* obase = ctxh + (size_t)(bb * SEQ + q0 + q0w) * DMODEL + hh * HDIM;
    const float inv0 = 1.0f / l_i[0];
    const float inv1 = 1.0f / l_i[1];
    #pragma unroll
    for (int nt = 0; nt < 8; ++nt) {
        const int col = nt * 8 + 2 * c0;
        *(uint32_t*)(obase + (size_t)r0 * DMODEL + col) =
            pack_h2(oacc[nt][0] * inv0, oacc[nt][1] * inv0);
        *(uint32_t*)(obase + (size_t)(r0 + 8) * DMODEL + col) =
            pack_h2(oacc[nt][2] * inv1, oacc[nt][3] * inv1);
    }
}

// =====================================================================
extern "C" void kernel_launch(void* const* d_in, const int* in_sizes, int n_in,
                              void* d_out, int out_size)
{
    const float* x  = (const float*)d_in[0];
    const float* Wq = (const float*)d_in[1];
    const float* Wk = (const float*)d_in[2];
    const float* Wv = (const float*)d_in[3];
    const float* Wo = (const float*)d_in[4];
    const float* bo = (const float*)d_in[5];
    float* out = (float*)d_out;

    float *qkv = nullptr;
    __half *xh = nullptr, *ctxh = nullptr;
    uint32_t *btf = nullptr, *wotf = nullptr;
    cudaGetSymbolAddress((void**)&qkv,  g_qkv);
    cudaGetSymbolAddress((void**)&xh,   g_xh);
    cudaGetSymbolAddress((void**)&ctxh, g_ctxh);
    cudaGetSymbolAddress((void**)&btf,  g_btf);
    cudaGetSymbolAddress((void**)&wotf, g_wotf);
    cudaFuncSetAttribute(attn_kernel,
                         cudaFuncAttributeMaxDynamicSharedMemorySize, ATT_SMEM_BYTES);
    cudaFuncSetAttribute(gemm_mma,
                         cudaFuncAttributeMaxDynamicSharedMemorySize, GEMM_SMEM_BYTES);

    const size_t WF_MAT = (size_t)128 * 64 * 64;   // u32 per 1024x1024 matrix
    fragify_h<<<1024, 256>>>(Wq, btf + 0 * WF_MAT);
    fragify_h<<<1024, 256>>>(Wk, btf + 1 * WF_MAT);
    fragify_h<<<1024, 256>>>(Wv, btf + 2 * WF_MAT);
    fragify_h<<<1024, 256>>>(Wo, wotf);
    to_half<<<(ROWS * DMODEL) / (256 * 4), 256>>>(x, xh);

    // QKV fused projection: [8192,1024] @ fused W -> g_qkv [8192][3072] (fp32)
    gemm_mma<<<dim3(3072 / 128, ROWS / 128), 256, GEMM_SMEM_BYTES>>>(
        xh, btf, qkv, nullptr, ROWS, 3072, DMODEL, DMODEL, QKV_LD);

    attn_kernel<<<dim3(SEQ / 128, BATCH * NHEADS), 256, ATT_SMEM_BYTES>>>(qkv, ctxh);

    // output projection + bias
    gemm_mma<<<dim3(DMODEL / 128, ROWS / 128), 256, GEMM_SMEM_BYTES>>>(
        ctxh, wotf, out, bo, ROWS, DMODEL, DMODEL, DMODEL, DMODEL);
}